// round 2
// baseline (speedup 1.0000x reference)
#include <cuda_runtime.h>

#define GRID_C 8
#define VOX    128
#define NB     16

// Coarse flow field after cumsum: [b][c][d][h][w], 16*3*512 floats = 96 KB
__device__ float g_flow[NB * 3 * GRID_C * GRID_C * GRID_C];

// ---------------------------------------------------------------------------
// Kernel 1: axis-wise cumsum of the 8^3 coarse flow + per-channel offset.
//   c=0: cumsum over w (axis 3) + ox
//   c=1: cumsum over h (axis 2) + oy
//   c=2: cumsum over d (axis 1) + oz
// One thread per 8-element line: 16*3*64 = 3072 threads.
// ---------------------------------------------------------------------------
__global__ void cumsum_kernel(const float* __restrict__ x,
                              const float* __restrict__ ox,
                              const float* __restrict__ oy,
                              const float* __restrict__ oz) {
    int t = blockIdx.x * blockDim.x + threadIdx.x;
    if (t >= NB * 3 * 64) return;
    int b = t / (3 * 64);
    int r = t % (3 * 64);
    int c = r / 64;
    int l = r % 64;

    float off = (c == 0) ? __ldg(ox) : (c == 1) ? __ldg(oy) : __ldg(oz);

    const float* src = x      + ((b * 3 + c) * 512);
    float*       dst = g_flow + ((b * 3 + c) * 512);

    int base, stride;
    if (c == 0)      { int d = l >> 3, h = l & 7; base = d * 64 + h * 8; stride = 1;  }
    else if (c == 1) { int d = l >> 3, w = l & 7; base = d * 64 + w;     stride = 8;  }
    else             { int h = l >> 3, w = l & 7; base = h * 8 + w;      stride = 64; }

    float acc = off;
#pragma unroll
    for (int i = 0; i < 8; i++) {
        acc += src[base + i * stride];
        dst[base + i * stride] = acc;
    }
}

// ---------------------------------------------------------------------------
// Kernel 2: fused trilinear-upsample of flow + trilinear grid-sample of src.
// Block = one output x-row (128 threads) at fixed (y, z, b).
// jax.image.resize 'trilinear' 8->128 == sample at s=(i+0.5)/16-0.5 clamped
// to [0,7] (edge-weight renormalization is exactly a clamp).
// (sy,sz) are uniform per row -> threads 0..95 each load ONE of the 96 coarse
// corner values (3ch x 8x x 4corners) into smem; 24 threads then combine the
// 4 z/y corners into the 3x8 x-line. Removes the serialized 4-LDG chain.
// ---------------------------------------------------------------------------
__global__ void __launch_bounds__(VOX)
warp_kernel(const float* __restrict__ src, float* __restrict__ out) {
    const int x = threadIdx.x;
    const int y = blockIdx.x;
    const int z = blockIdx.y;
    const int b = blockIdx.z;

    __shared__ float s_c[3][2][2][GRID_C];   // [c][dz][dy][jx]
    __shared__ float s_row[3][GRID_C];

    const float inv16 = 0.0625f;
    float syf = fminf(fmaxf((y + 0.5f) * inv16 - 0.5f, 0.0f), 7.0f);
    float szf = fminf(fmaxf((z + 0.5f) * inv16 - 0.5f, 0.0f), 7.0f);
    int jy0 = min((int)syf, 6); float fy = syf - (float)jy0;
    int jz0 = min((int)szf, 6); float fz = szf - (float)jz0;

    if (threadIdx.x < 96) {
        int c    = threadIdx.x / 32;           // channel
        int rem  = threadIdx.x & 31;
        int corn = rem >> 3;                   // 0..3 = (dz,dy)
        int jx   = rem & 7;
        int dz   = corn >> 1, dy = corn & 1;
        const float* f = g_flow + ((b * 3 + c) * 512);
        s_c[c][dz][dy][jx] = f[(jz0 + dz) * 64 + (jy0 + dy) * 8 + jx];
    }
    __syncthreads();
    if (threadIdx.x < 24) {
        int c  = threadIdx.x >> 3;
        int jx = threadIdx.x & 7;
        float v0 = s_c[c][0][0][jx] + fy * (s_c[c][0][1][jx] - s_c[c][0][0][jx]);
        float v1 = s_c[c][1][0][jx] + fy * (s_c[c][1][1][jx] - s_c[c][1][0][jx]);
        s_row[c][jx] = v0 + fz * (v1 - v0);
    }
    __syncthreads();

    float sxf = fminf(fmaxf((x + 0.5f) * inv16 - 0.5f, 0.0f), 7.0f);
    int jx0 = min((int)sxf, 6); float fx = sxf - (float)jx0;

    float fl_x = s_row[0][jx0] + fx * (s_row[0][jx0 + 1] - s_row[0][jx0]);
    float fl_y = s_row[1][jx0] + fx * (s_row[1][jx0 + 1] - s_row[1][jx0]);
    float fl_z = s_row[2][jx0] + fx * (s_row[2][jx0 + 1] - s_row[2][jx0]);

    // grid_sample coords: g = ((flow + 1) * 128 - 1) * 0.5
    float gx = (fl_x + 1.0f) * 64.0f - 0.5f;
    float gy = (fl_y + 1.0f) * 64.0f - 0.5f;
    float gz = (fl_z + 1.0f) * 64.0f - 0.5f;

    float x0f = floorf(gx), y0f = floorf(gy), z0f = floorf(gz);
    int ix0 = (int)x0f, iy0 = (int)y0f, iz0 = (int)z0f;
    float fxs = gx - x0f, fys = gy - y0f, fzs = gz - z0f;

    const float* sb = src + (size_t)b * VOX * VOX * VOX;
    float acc = 0.0f;

#pragma unroll
    for (int dz = 0; dz < 2; dz++) {
        int zi = iz0 + dz;
        if ((unsigned)zi >= VOX) continue;
        float wz = dz ? fzs : 1.0f - fzs;
#pragma unroll
        for (int dy = 0; dy < 2; dy++) {
            int yi = iy0 + dy;
            if ((unsigned)yi >= VOX) continue;
            float wzy = wz * (dy ? fys : 1.0f - fys);
            const float* row = sb + ((size_t)zi * VOX + yi) * VOX;
            float vx = 0.0f;
            if ((unsigned)ix0       < VOX) vx  = __ldg(row + ix0)     * (1.0f - fxs);
            if ((unsigned)(ix0 + 1) < VOX) vx += __ldg(row + ix0 + 1) * fxs;
            acc += wzy * vx;
        }
    }

    out[(((size_t)b * VOX + z) * VOX + y) * VOX + x] = acc;
}

// ---------------------------------------------------------------------------
extern "C" void kernel_launch(void* const* d_in, const int* in_sizes, int n_in,
                              void* d_out, int out_size) {
    const float* x   = (const float*)d_in[0];   // (16,3,8,8,8)
    const float* src = (const float*)d_in[1];   // (16,128,128,128)
    const float* ox  = (const float*)d_in[2];   // scalar
    const float* oy  = (const float*)d_in[3];   // scalar
    const float* oz  = (const float*)d_in[4];   // scalar

    cumsum_kernel<<<12, 256>>>(x, ox, oy, oz);

    dim3 grid(VOX, VOX, NB);
    warp_kernel<<<grid, VOX>>>(src, (float*)d_out);
}

// round 4
// speedup vs baseline: 1.0469x; 1.0469x over previous
#include <cuda_runtime.h>

#define GRID_C 8
#define VOX    128
#define NB     16

// Coarse flow field after cumsum: [b][c][d][h][w], 16*3*512 floats = 96 KB
__device__ float g_flow[NB * 3 * GRID_C * GRID_C * GRID_C];

// ---------------------------------------------------------------------------
// Kernel 1: axis-wise cumsum of the 8^3 coarse flow + per-channel offset.
// ---------------------------------------------------------------------------
__global__ void cumsum_kernel(const float* __restrict__ x,
                              const float* __restrict__ ox,
                              const float* __restrict__ oy,
                              const float* __restrict__ oz) {
    int t = blockIdx.x * blockDim.x + threadIdx.x;
    if (t >= NB * 3 * 64) return;
    int b = t / (3 * 64);
    int r = t % (3 * 64);
    int c = r / 64;
    int l = r % 64;

    float off = (c == 0) ? __ldg(ox) : (c == 1) ? __ldg(oy) : __ldg(oz);

    const float* src = x      + ((b * 3 + c) * 512);
    float*       dst = g_flow + ((b * 3 + c) * 512);

    int base, stride;
    if (c == 0)      { int d = l >> 3, h = l & 7; base = d * 64 + h * 8; stride = 1;  }
    else if (c == 1) { int d = l >> 3, w = l & 7; base = d * 64 + w;     stride = 8;  }
    else             { int h = l >> 3, w = l & 7; base = h * 8 + w;      stride = 64; }

    float acc = off;
#pragma unroll
    for (int i = 0; i < 8; i++) {
        acc += src[base + i * stride];
        dst[base + i * stride] = acc;
    }
}

// ---------------------------------------------------------------------------
// Kernel 2: fused trilinear-upsample of flow + trilinear grid-sample.
// Block = one output x-row (128 threads) at fixed (y, z, b).
// Gather: x-tap pair fetched as ONE aligned float2 (+ masked scalar for the
// odd-straddle case); all loads issued up-front fully predicated (MLP up to 8).
// ---------------------------------------------------------------------------
__global__ void __launch_bounds__(VOX)
warp_kernel(const float* __restrict__ src, float* __restrict__ out) {
    const int x = threadIdx.x;
    const int y = blockIdx.x;
    const int z = blockIdx.y;
    const int b = blockIdx.z;

    __shared__ float s_c[3][2][2][GRID_C];   // [c][dz][dy][jx]
    __shared__ float s_row[3][GRID_C];

    const float inv16 = 0.0625f;
    float syf = fminf(fmaxf((y + 0.5f) * inv16 - 0.5f, 0.0f), 7.0f);
    float szf = fminf(fmaxf((z + 0.5f) * inv16 - 0.5f, 0.0f), 7.0f);
    int jy0 = min((int)syf, 6); float fy = syf - (float)jy0;
    int jz0 = min((int)szf, 6); float fz = szf - (float)jz0;

    if (threadIdx.x < 96) {
        int c    = threadIdx.x / 32;
        int rem  = threadIdx.x & 31;
        int corn = rem >> 3;
        int jx   = rem & 7;
        int dz   = corn >> 1, dy = corn & 1;
        const float* f = g_flow + ((b * 3 + c) * 512);
        s_c[c][dz][dy][jx] = f[(jz0 + dz) * 64 + (jy0 + dy) * 8 + jx];
    }
    __syncthreads();
    if (threadIdx.x < 24) {
        int c  = threadIdx.x >> 3;
        int jx = threadIdx.x & 7;
        float v0 = s_c[c][0][0][jx] + fy * (s_c[c][0][1][jx] - s_c[c][0][0][jx]);
        float v1 = s_c[c][1][0][jx] + fy * (s_c[c][1][1][jx] - s_c[c][1][0][jx]);
        s_row[c][jx] = v0 + fz * (v1 - v0);
    }
    __syncthreads();

    float sxf = fminf(fmaxf((x + 0.5f) * inv16 - 0.5f, 0.0f), 7.0f);
    int jx0 = min((int)sxf, 6); float fx = sxf - (float)jx0;

    float fl_x = s_row[0][jx0] + fx * (s_row[0][jx0 + 1] - s_row[0][jx0]);
    float fl_y = s_row[1][jx0] + fx * (s_row[1][jx0 + 1] - s_row[1][jx0]);
    float fl_z = s_row[2][jx0] + fx * (s_row[2][jx0 + 1] - s_row[2][jx0]);

    // grid_sample coords: g = ((flow + 1) * 128 - 1) * 0.5
    float gx = (fl_x + 1.0f) * 64.0f - 0.5f;
    float gy = (fl_y + 1.0f) * 64.0f - 0.5f;
    float gz = (fl_z + 1.0f) * 64.0f - 0.5f;

    float x0f = floorf(gx), y0f = floorf(gy), z0f = floorf(gz);
    int ix0 = (int)x0f, iy0 = (int)y0f, iz0 = (int)z0f;
    float fxs = gx - x0f, fys = gy - y0f, fzs = gz - z0f;

    // ---- paired x-tap setup ----
    // Aligned float2 at e0 = (ix0 >= 0 ? ix0 : ix0+1) >> 1 covers:
    //   ix0 even : both taps (A.x, A.y)
    //   ix0 odd  : tap-a in A.y; tap-b needs the scalar straddle load
    //   ix0 = -1 : e0 = 0, tap-b = A.x (wa = 0 kills tap-a)
    bool v0   = (unsigned)ix0       < (unsigned)VOX;
    bool v1   = (unsigned)(ix0 + 1) < (unsigned)VOX;
    bool xany = v0 | v1;
    int  e0   = (v0 ? ix0 : (ix0 + 1)) >> 1;
    bool odd  = (ix0 & 1) && v0;        // straddle only for odd in-bounds ix0
    float wa  = v0 ? (1.0f - fxs) : 0.0f;
    float wb  = v1 ? fxs          : 0.0f;

    const float2* sb2 = (const float2*)(src + (size_t)b * (VOX * VOX * VOX));
    int base = iz0 * (VOX * VOX / 2) + iy0 * (VOX / 2) + e0;

    bool zv0 = (unsigned)iz0       < (unsigned)VOX;
    bool zv1 = (unsigned)(iz0 + 1) < (unsigned)VOX;
    bool yv0 = (unsigned)iy0       < (unsigned)VOX;
    bool yv1 = (unsigned)(iy0 + 1) < (unsigned)VOX;

    bool rv[4];
    rv[0] = zv0 & yv0 & xany;
    rv[1] = zv0 & yv1 & xany;
    rv[2] = zv1 & yv0 & xany;
    rv[3] = zv1 & yv1 & xany;
    const int off[4] = { 0, VOX / 2, VOX * VOX / 2, VOX * VOX / 2 + VOX / 2 };

    // Batch-issue all primary loads, fully predicated.
    float2 A[4];
#pragma unroll
    for (int k = 0; k < 4; k++) {
        A[k] = make_float2(0.0f, 0.0f);
        if (rv[k]) A[k] = __ldg(sb2 + (base + off[k]));
    }
    // Straddle loads (only when ix0 odd in-bounds AND ix0+1 in-bounds).
    bool need2 = odd & v1;
    float Bx[4];
#pragma unroll
    for (int k = 0; k < 4; k++) {
        Bx[k] = 0.0f;
        if (rv[k] & need2) Bx[k] = __ldg((const float*)(sb2 + (base + off[k] + 1)));
    }

    float wy0 = 1.0f - fys, wy1 = fys;
    float wz0 = 1.0f - fzs, wz1 = fzs;
    float wk[4] = { wz0 * wy0, wz0 * wy1, wz1 * wy0, wz1 * wy1 };

    float acc = 0.0f;
#pragma unroll
    for (int k = 0; k < 4; k++) {
        float a  = odd ? A[k].y : A[k].x;                 // tap-a value
        float bb = odd ? Bx[k]  : A[k].y;                 // tap-b value
        // ix0 == -1 case: wa=0, tap-b must be A.x (e0 aligned at ix0+1 even)
        if (!v0) bb = A[k].x;
        acc += wk[k] * (wa * a + wb * bb);
    }

    out[(((size_t)b * VOX + z) * VOX + y) * VOX + x] = acc;
}

// ---------------------------------------------------------------------------
extern "C" void kernel_launch(void* const* d_in, const int* in_sizes, int n_in,
                              void* d_out, int out_size) {
    const float* x   = (const float*)d_in[0];   // (16,3,8,8,8)
    const float* src = (const float*)d_in[1];   // (16,128,128,128)
    const float* ox  = (const float*)d_in[2];   // scalar
    const float* oy  = (const float*)d_in[3];   // scalar
    const float* oz  = (const float*)d_in[4];   // scalar

    cumsum_kernel<<<12, 256>>>(x, ox, oy, oz);

    dim3 grid(VOX, VOX, NB);
    warp_kernel<<<grid, VOX>>>(src, (float*)d_out);
}